// round 1
// baseline (speedup 1.0000x reference)
#include <cuda_runtime.h>
#include <math.h>

// Problem constants
#define Bn 4
#define Sn 1024
#define Tn 4096          // Bn*Sn tokens
#define Hn 512
#define En 8
#define Fn 2048
#define NBUCK 32         // En*Bn  (expert, batch) buckets
#define CAPn 1024        // max tokens per bucket = Sn

// ---------------- scratch (__device__ globals; no allocation) ----------------
__device__ float g_K [(size_t)En*Tn*Hn];        // 64 MB
__device__ float g_V [(size_t)En*Tn*Hn];        // 64 MB
__device__ float g_q [(size_t)NBUCK*CAPn*Hn];   // 64 MB
__device__ float g_sc[(size_t)NBUCK*CAPn*Sn];   // 128 MB
__device__ float g_h1[(size_t)NBUCK*CAPn*Fn];   // 256 MB
__device__ float g_h2[(size_t)NBUCK*CAPn*Hn];   // 64 MB
__device__ float g_a [(size_t)NBUCK*CAPn*Hn];   // 64 MB
__device__ int   g_cnt[NBUCK];
__device__ int   g_tok[NBUCK*CAPn];
__device__ float g_wt [NBUCK*CAPn];
__device__ float g_imp[En];

// ---------------- small kernels ----------------
__global__ void reset_kernel() {
    int i = threadIdx.x;
    if (i < NBUCK) g_cnt[i] = 0;
    if (i < En)    g_imp[i] = 0.f;
}

__global__ void zero_kernel(float* __restrict__ out, int n) {
    int i = blockIdx.x * blockDim.x + threadIdx.x;
    if (i < n) out[i] = 0.f;
}

// Router: one warp per token. logits = x @ Wg + bg -> softmax -> top2 -> buckets.
__global__ void router_kernel(const float* __restrict__ x,
                              const float* __restrict__ Wg,
                              const float* __restrict__ bg)
{
    int warp = (blockIdx.x * blockDim.x + threadIdx.x) >> 5;
    int lane = threadIdx.x & 31;
    if (warp >= Tn) return;
    const int t = warp;

    float acc[En];
#pragma unroll
    for (int e = 0; e < En; e++) acc[e] = 0.f;

    for (int h = lane; h < Hn; h += 32) {
        float xv = x[(size_t)t * Hn + h];
        float4 w0 = *(const float4*)(Wg + (size_t)h * En);
        float4 w1 = *(const float4*)(Wg + (size_t)h * En + 4);
        acc[0] += xv * w0.x; acc[1] += xv * w0.y; acc[2] += xv * w0.z; acc[3] += xv * w0.w;
        acc[4] += xv * w1.x; acc[5] += xv * w1.y; acc[6] += xv * w1.z; acc[7] += xv * w1.w;
    }
#pragma unroll
    for (int off = 16; off > 0; off >>= 1) {
#pragma unroll
        for (int e = 0; e < En; e++)
            acc[e] += __shfl_xor_sync(0xffffffffu, acc[e], off);
    }
    if (lane != 0) return;

    float p[En];
    float m = -1e30f;
#pragma unroll
    for (int e = 0; e < En; e++) { p[e] = acc[e] + bg[e]; m = fmaxf(m, p[e]); }
    float s = 0.f;
#pragma unroll
    for (int e = 0; e < En; e++) { p[e] = expf(p[e] - m); s += p[e]; }
    float inv = 1.0f / s;
#pragma unroll
    for (int e = 0; e < En; e++) { p[e] *= inv; atomicAdd(&g_imp[e], p[e]); }

    // top-2 (ties -> lower index, matching lax.top_k)
    int i1 = 0;
#pragma unroll
    for (int e = 1; e < En; e++) if (p[e] > p[i1]) i1 = e;
    int i2 = (i1 == 0) ? 1 : 0;
#pragma unroll
    for (int e = 0; e < En; e++) if (e != i1 && p[e] > p[i2]) i2 = e;

    float denom = p[i1] + p[i2];
    int b = t >> 10;  // / Sn
    int bk1 = i1 * Bn + b;
    int pos1 = atomicAdd(&g_cnt[bk1], 1);
    g_tok[bk1 * CAPn + pos1] = t;
    g_wt [bk1 * CAPn + pos1] = p[i1] / denom;
    int bk2 = i2 * Bn + b;
    int pos2 = atomicAdd(&g_cnt[bk2], 1);
    g_tok[bk2 * CAPn + pos2] = t;
    g_wt [bk2 * CAPn + pos2] = p[i2] / denom;
}

// Row softmax over scores (length Sn = 1024), 256 threads, 4 elems/thread.
__global__ void softmax_kernel()
{
    int bkt = blockIdx.x >> 10;
    int r   = blockIdx.x & (CAPn - 1);
    if (r >= g_cnt[bkt]) return;
    float* row = g_sc + ((size_t)bkt * CAPn + r) * Sn;
    int tid = threadIdx.x;

    float4 v = *(float4*)(row + tid * 4);
    float m = fmaxf(fmaxf(v.x, v.y), fmaxf(v.z, v.w));

    __shared__ float sm[8];
    __shared__ float bcast;
#pragma unroll
    for (int off = 16; off > 0; off >>= 1)
        m = fmaxf(m, __shfl_xor_sync(0xffffffffu, m, off));
    if ((tid & 31) == 0) sm[tid >> 5] = m;
    __syncthreads();
    if (tid == 0) {
        float mm = sm[0];
#pragma unroll
        for (int k = 1; k < 8; k++) mm = fmaxf(mm, sm[k]);
        bcast = mm;
    }
    __syncthreads();
    float bm = bcast;

    v.x = expf(v.x - bm); v.y = expf(v.y - bm);
    v.z = expf(v.z - bm); v.w = expf(v.w - bm);
    float ssum = v.x + v.y + v.z + v.w;
#pragma unroll
    for (int off = 16; off > 0; off >>= 1)
        ssum += __shfl_xor_sync(0xffffffffu, ssum, off);
    if ((tid & 31) == 0) sm[tid >> 5] = ssum;
    __syncthreads();
    if (tid == 0) {
        float tt = 0.f;
#pragma unroll
        for (int k = 0; k < 8; k++) tt += sm[k];
        bcast = 1.0f / tt;
    }
    __syncthreads();
    float invs = bcast;
    v.x *= invs; v.y *= invs; v.z *= invs; v.w *= invs;
    *(float4*)(row + tid * 4) = v;
}

__global__ void finalize_kernel(float* __restrict__ out, int out_size)
{
    if (threadIdx.x == 0 && out_size > Tn * Hn) {
        float loss = 0.f;
        for (int e = 0; e < En; e++) {
            int a = 0;
            for (int b = 0; b < Bn; b++) a += g_cnt[e * Bn + b];
            loss += ((float)a / (float)Tn) * (g_imp[e] / (float)Tn);
        }
        out[Tn * Hn] = (float)En * loss;
    }
}

// ---------------- workhorse GEMM: 128x128x16 tile, 256 thr, 8x8/thread ----------------
enum { KK = 0, KV = 1, KQ = 2, KF1 = 3, KF2 = 4, KSC = 5, KPV = 6, KO = 7 };

template <int KIND>
__global__ __launch_bounds__(256, 2)
void gemm_kernel(const float* __restrict__ Xin, const float* __restrict__ W,
                 const float* __restrict__ bias, float* __restrict__ outp)
{
    constexpr bool BUCKET = (KIND != KK && KIND != KV);
    constexpr bool GATHER = (KIND == KQ || KIND == KF1);
    constexpr bool TRANSB = (KIND == KSC);
    constexpr int  KDIM = (KIND == KF2) ? Fn : (KIND == KPV ? Sn : Hn);
    constexpr int  LDB  = (KIND == KF1) ? Fn : Hn;
    constexpr int  NDIM = (KIND == KF1) ? Fn : (KIND == KSC ? Sn : Hn);

    const int tid = threadIdx.x;
    const int z = blockIdx.z;
    int e, bb = 0, M;
    if (BUCKET) {
        e = z >> 2; bb = z & 3;
        M = g_cnt[z];
        if ((int)(blockIdx.x * 128) >= M) return;
    } else {
        e = z; M = Tn;
    }

    const float* Bptr;
    if      (KIND == KK || KIND == KV || KIND == KQ || KIND == KO) Bptr = W + (size_t)e * Hn * Hn;
    else if (KIND == KF1) Bptr = W + (size_t)e * Hn * Fn;
    else if (KIND == KF2) Bptr = W + (size_t)e * Fn * Hn;
    else if (KIND == KSC) Bptr = g_K + ((size_t)e * Tn + (size_t)bb * Sn) * Hn;
    else                  Bptr = g_V + ((size_t)e * Tn + (size_t)bb * Sn) * Hn;  // KPV

    const int row0 = blockIdx.x * 128;
    const int col0 = blockIdx.y * 128;

    // A loader: row lr, k-offset lk8
    const int lr  = tid >> 1;
    const int lk8 = (tid & 1) * 8;
    const int grow = row0 + lr;
    const bool aval = grow < M;
    const float* aRow = nullptr;
    if (aval) {
        if      (GATHER)              aRow = Xin + (size_t)g_tok[z * CAPn + grow] * Hn;
        else if (KIND == KK || KIND == KV) aRow = Xin + (size_t)grow * Hn;
        else if (KIND == KF2)         aRow = g_h1 + ((size_t)z * CAPn + grow) * Fn;
        else if (KIND == KSC)         aRow = g_q  + ((size_t)z * CAPn + grow) * Hn;
        else if (KIND == KPV)         aRow = g_sc + ((size_t)z * CAPn + grow) * Sn;
        else                          aRow = g_a  + ((size_t)z * CAPn + grow) * Hn;  // KO
    }

    __shared__ __align__(16) float As[16][132];  // k-transposed A tile
    __shared__ __align__(16) float Bs[16][132];

    float acc[8][8];
#pragma unroll
    for (int i = 0; i < 8; i++)
#pragma unroll
        for (int j = 0; j < 8; j++) acc[i][j] = 0.f;

    const int ty = tid >> 4, tx = tid & 15;

    for (int kt = 0; kt < KDIM; kt += 16) {
        float4 a0 = make_float4(0.f, 0.f, 0.f, 0.f), a1 = a0;
        if (aval) {
            a0 = *(const float4*)(aRow + kt + lk8);
            a1 = *(const float4*)(aRow + kt + lk8 + 4);
        }
        As[lk8 + 0][lr] = a0.x; As[lk8 + 1][lr] = a0.y;
        As[lk8 + 2][lr] = a0.z; As[lk8 + 3][lr] = a0.w;
        As[lk8 + 4][lr] = a1.x; As[lk8 + 5][lr] = a1.y;
        As[lk8 + 6][lr] = a1.z; As[lk8 + 7][lr] = a1.w;

        if (!TRANSB) {
            const int bk = tid >> 4;
            const int bc = (tid & 15) * 8;
            const float* src = Bptr + (size_t)(kt + bk) * LDB + col0 + bc;
            *(float4*)&Bs[bk][bc]     = *(const float4*)(src);
            *(float4*)&Bs[bk][bc + 4] = *(const float4*)(src + 4);
        } else {
            const int bc  = tid >> 1;
            const int bk8 = (tid & 1) * 8;
            const float* src = Bptr + (size_t)(col0 + bc) * LDB + kt + bk8;
            float4 b0 = *(const float4*)src;
            float4 b1 = *(const float4*)(src + 4);
            Bs[bk8 + 0][bc] = b0.x; Bs[bk8 + 1][bc] = b0.y;
            Bs[bk8 + 2][bc] = b0.z; Bs[bk8 + 3][bc] = b0.w;
            Bs[bk8 + 4][bc] = b1.x; Bs[bk8 + 5][bc] = b1.y;
            Bs[bk8 + 6][bc] = b1.z; Bs[bk8 + 7][bc] = b1.w;
        }
        __syncthreads();

#pragma unroll
        for (int kk = 0; kk < 16; kk++) {
            float4 av0 = *(const float4*)&As[kk][ty * 8];
            float4 av1 = *(const float4*)&As[kk][ty * 8 + 4];
            float4 bv0 = *(const float4*)&Bs[kk][tx * 8];
            float4 bv1 = *(const float4*)&Bs[kk][tx * 8 + 4];
            float aa[8]  = {av0.x, av0.y, av0.z, av0.w, av1.x, av1.y, av1.z, av1.w};
            float bbv[8] = {bv0.x, bv0.y, bv0.z, bv0.w, bv1.x, bv1.y, bv1.z, bv1.w};
#pragma unroll
            for (int i = 0; i < 8; i++)
#pragma unroll
                for (int j = 0; j < 8; j++)
                    acc[i][j] = fmaf(aa[i], bbv[j], acc[i][j]);
        }
        __syncthreads();
    }

    // ---------------- epilogue ----------------
    const int rb = row0 + ty * 8;
    const int cb = col0 + tx * 8;

    float bvals[8];
    if (KIND != KSC && KIND != KPV) {
        const float* bp = bias + (size_t)e * NDIM + cb;
#pragma unroll
        for (int j = 0; j < 8; j++) bvals[j] = bp[j];
    }

    if (KIND == KK || KIND == KV) {
        float* C = (KIND == KK ? g_K : g_V) + (size_t)e * Tn * Hn;
#pragma unroll
        for (int i = 0; i < 8; i++) {
            int r = rb + i;
#pragma unroll
            for (int j = 0; j < 8; j++)
                C[(size_t)r * Hn + cb + j] = acc[i][j] + bvals[j];
        }
    } else if (KIND == KQ) {
        float* C = g_q + (size_t)z * CAPn * Hn;
#pragma unroll
        for (int i = 0; i < 8; i++) {
            int r = rb + i;
            if (r < M)
#pragma unroll
                for (int j = 0; j < 8; j++)
                    C[(size_t)r * Hn + cb + j] = acc[i][j] + bvals[j];
        }
    } else if (KIND == KF1) {
        float* C = g_h1 + (size_t)z * CAPn * Fn;
#pragma unroll
        for (int i = 0; i < 8; i++) {
            int r = rb + i;
            if (r < M)
#pragma unroll
                for (int j = 0; j < 8; j++) {
                    float v = acc[i][j] + bvals[j];
                    v = 0.5f * v * (1.0f + erff(v * 0.70710678118654752f));  // exact gelu
                    C[(size_t)r * Fn + cb + j] = v;
                }
        }
    } else if (KIND == KF2) {
        float* C = g_h2 + (size_t)z * CAPn * Hn;
#pragma unroll
        for (int i = 0; i < 8; i++) {
            int r = rb + i;
            if (r < M)
#pragma unroll
                for (int j = 0; j < 8; j++)
                    C[(size_t)r * Hn + cb + j] = acc[i][j] + bvals[j];
        }
    } else if (KIND == KSC) {
        const float scl = 0.044194173824159216f;  // 1/sqrt(512)
        float* C = g_sc + (size_t)z * CAPn * Sn;
#pragma unroll
        for (int i = 0; i < 8; i++) {
            int r = rb + i;
            if (r < M)
#pragma unroll
                for (int j = 0; j < 8; j++)
                    C[(size_t)r * Sn + cb + j] = acc[i][j] * scl;
        }
    } else if (KIND == KPV) {
        float* C = g_a + (size_t)z * CAPn * Hn;
#pragma unroll
        for (int i = 0; i < 8; i++) {
            int r = rb + i;
            if (r < M)
#pragma unroll
                for (int j = 0; j < 8; j++)
                    C[(size_t)r * Hn + cb + j] = acc[i][j];
        }
    } else {  // KO: o-proj + ffn add + weighted scatter
        const float* h2 = g_h2 + (size_t)z * CAPn * Hn;
#pragma unroll
        for (int i = 0; i < 8; i++) {
            int r = rb + i;
            if (r < M) {
                int tok = g_tok[z * CAPn + r];
                float w = g_wt[z * CAPn + r];
                float* od = outp + (size_t)tok * Hn;
#pragma unroll
                for (int j = 0; j < 8; j++) {
                    float v = acc[i][j] + bvals[j] + h2[(size_t)r * Hn + cb + j];
                    atomicAdd(&od[cb + j], w * v);
                }
            }
        }
    }
}

// ---------------- launch ----------------
extern "C" void kernel_launch(void* const* d_in, const int* in_sizes, int n_in,
                              void* d_out, int out_size)
{
    const float* x    = (const float*)d_in[0];
    const float* Wg   = (const float*)d_in[1];
    const float* bg   = (const float*)d_in[2];
    const float* fc1w = (const float*)d_in[3];
    const float* fc1b = (const float*)d_in[4];
    const float* fc2w = (const float*)d_in[5];
    const float* fc2b = (const float*)d_in[6];
    const float* qw   = (const float*)d_in[7];
    const float* qb   = (const float*)d_in[8];
    const float* kw   = (const float*)d_in[9];
    const float* kb   = (const float*)d_in[10];
    const float* vw   = (const float*)d_in[11];
    const float* vb   = (const float*)d_in[12];
    const float* ow   = (const float*)d_in[13];
    const float* ob   = (const float*)d_in[14];
    float* out = (float*)d_out;

    reset_kernel<<<1, 64>>>();
    zero_kernel<<<(out_size + 255) / 256, 256>>>(out, out_size);
    router_kernel<<<Tn / 8, 256>>>(x, Wg, bg);

    dim3 gkv(Tn / 128, Hn / 128, En);
    gemm_kernel<KK><<<gkv, 256>>>(x, kw, kb, nullptr);
    gemm_kernel<KV><<<gkv, 256>>>(x, vw, vb, nullptr);

    dim3 gq(CAPn / 128, Hn / 128, NBUCK);
    gemm_kernel<KQ><<<gq, 256>>>(x, qw, qb, nullptr);

    dim3 gf1(CAPn / 128, Fn / 128, NBUCK);
    gemm_kernel<KF1><<<gf1, 256>>>(x, fc1w, fc1b, nullptr);

    dim3 gf2(CAPn / 128, Hn / 128, NBUCK);
    gemm_kernel<KF2><<<gf2, 256>>>(nullptr, fc2w, fc2b, nullptr);

    dim3 gsc(CAPn / 128, Sn / 128, NBUCK);
    gemm_kernel<KSC><<<gsc, 256>>>(nullptr, nullptr, nullptr, nullptr);

    softmax_kernel<<<NBUCK * CAPn, 256>>>();

    dim3 gpv(CAPn / 128, Hn / 128, NBUCK);
    gemm_kernel<KPV><<<gpv, 256>>>(nullptr, nullptr, nullptr, nullptr);

    dim3 go(CAPn / 128, Hn / 128, NBUCK);
    gemm_kernel<KO><<<go, 256>>>(nullptr, ow, ob, out);

    finalize_kernel<<<1, 32>>>(out, out_size);
}

// round 3
// speedup vs baseline: 2.5381x; 2.5381x over previous
#include <cuda_runtime.h>
#include <math.h>
#include <stdint.h>

// Problem constants
#define Bn 4
#define Sn 1024
#define Tn 4096          // Bn*Sn tokens
#define Hn 512
#define En 8
#define Fn 2048
#define NBUCK 32         // En*Bn  (expert, batch) buckets
#define CAPn 1024        // max tokens per bucket = Sn

// ---------------- scratch (__device__ globals; no allocation) ----------------
__device__ float g_K [(size_t)En*Tn*Hn];        // 64 MB
__device__ float g_V [(size_t)En*Tn*Hn];        // 64 MB
__device__ float g_q [(size_t)NBUCK*CAPn*Hn];   // 64 MB
__device__ float g_sc[(size_t)NBUCK*CAPn*Sn];   // 128 MB
__device__ float g_h1[(size_t)NBUCK*CAPn*Fn];   // 256 MB
__device__ float g_h2[(size_t)NBUCK*CAPn*Hn];   // 64 MB
__device__ float g_a [(size_t)NBUCK*CAPn*Hn];   // 64 MB
__device__ int   g_cnt[NBUCK];
__device__ int   g_tok[NBUCK*CAPn];
__device__ float g_wt [NBUCK*CAPn];
__device__ float g_imp[En];

// ---------------- small kernels ----------------
__global__ void reset_kernel() {
    int i = threadIdx.x;
    if (i < NBUCK) g_cnt[i] = 0;
    if (i < En)    g_imp[i] = 0.f;
}

__global__ void zero_kernel(float* __restrict__ out, int n) {
    int i = blockIdx.x * blockDim.x + threadIdx.x;
    if (i < n) out[i] = 0.f;
}

// Router: one warp per token. Exact fp32.
__global__ void router_kernel(const float* __restrict__ x,
                              const float* __restrict__ Wg,
                              const float* __restrict__ bg)
{
    int warp = (blockIdx.x * blockDim.x + threadIdx.x) >> 5;
    int lane = threadIdx.x & 31;
    if (warp >= Tn) return;
    const int t = warp;

    float acc[En];
#pragma unroll
    for (int e = 0; e < En; e++) acc[e] = 0.f;

    for (int h = lane; h < Hn; h += 32) {
        float xv = x[(size_t)t * Hn + h];
        float4 w0 = *(const float4*)(Wg + (size_t)h * En);
        float4 w1 = *(const float4*)(Wg + (size_t)h * En + 4);
        acc[0] += xv * w0.x; acc[1] += xv * w0.y; acc[2] += xv * w0.z; acc[3] += xv * w0.w;
        acc[4] += xv * w1.x; acc[5] += xv * w1.y; acc[6] += xv * w1.z; acc[7] += xv * w1.w;
    }
#pragma unroll
    for (int off = 16; off > 0; off >>= 1) {
#pragma unroll
        for (int e = 0; e < En; e++)
            acc[e] += __shfl_xor_sync(0xffffffffu, acc[e], off);
    }
    if (lane != 0) return;

    float p[En];
    float m = -1e30f;
#pragma unroll
    for (int e = 0; e < En; e++) { p[e] = acc[e] + bg[e]; m = fmaxf(m, p[e]); }
    float s = 0.f;
#pragma unroll
    for (int e = 0; e < En; e++) { p[e] = expf(p[e] - m); s += p[e]; }
    float inv = 1.0f / s;
#pragma unroll
    for (int e = 0; e < En; e++) { p[e] *= inv; atomicAdd(&g_imp[e], p[e]); }

    int i1 = 0;
#pragma unroll
    for (int e = 1; e < En; e++) if (p[e] > p[i1]) i1 = e;
    int i2 = (i1 == 0) ? 1 : 0;
#pragma unroll
    for (int e = 0; e < En; e++) if (e != i1 && p[e] > p[i2]) i2 = e;

    float denom = p[i1] + p[i2];
    int b = t >> 10;
    int bk1 = i1 * Bn + b;
    int pos1 = atomicAdd(&g_cnt[bk1], 1);
    g_tok[bk1 * CAPn + pos1] = t;
    g_wt [bk1 * CAPn + pos1] = p[i1] / denom;
    int bk2 = i2 * Bn + b;
    int pos2 = atomicAdd(&g_cnt[bk2], 1);
    g_tok[bk2 * CAPn + pos2] = t;
    g_wt [bk2 * CAPn + pos2] = p[i2] / denom;
}

// Row softmax over scores (length Sn = 1024), 256 threads, 4 elems/thread.
__global__ void softmax_kernel()
{
    int bkt = blockIdx.x >> 10;
    int r   = blockIdx.x & (CAPn - 1);
    if (r >= g_cnt[bkt]) return;
    float* row = g_sc + ((size_t)bkt * CAPn + r) * Sn;
    int tid = threadIdx.x;

    float4 v = *(float4*)(row + tid * 4);
    float m = fmaxf(fmaxf(v.x, v.y), fmaxf(v.z, v.w));

    __shared__ float sm[8];
    __shared__ float bcast;
#pragma unroll
    for (int off = 16; off > 0; off >>= 1)
        m = fmaxf(m, __shfl_xor_sync(0xffffffffu, m, off));
    if ((tid & 31) == 0) sm[tid >> 5] = m;
    __syncthreads();
    if (tid == 0) {
        float mm = sm[0];
#pragma unroll
        for (int k = 1; k < 8; k++) mm = fmaxf(mm, sm[k]);
        bcast = mm;
    }
    __syncthreads();
    float bm = bcast;

    v.x = expf(v.x - bm); v.y = expf(v.y - bm);
    v.z = expf(v.z - bm); v.w = expf(v.w - bm);
    float ssum = v.x + v.y + v.z + v.w;
#pragma unroll
    for (int off = 16; off > 0; off >>= 1)
        ssum += __shfl_xor_sync(0xffffffffu, ssum, off);
    if ((tid & 31) == 0) sm[tid >> 5] = ssum;
    __syncthreads();
    if (tid == 0) {
        float tt = 0.f;
#pragma unroll
        for (int k = 0; k < 8; k++) tt += sm[k];
        bcast = 1.0f / tt;
    }
    __syncthreads();
    float invs = bcast;
    v.x *= invs; v.y *= invs; v.z *= invs; v.w *= invs;
    *(float4*)(row + tid * 4) = v;
}

__global__ void finalize_kernel(float* __restrict__ out, int out_size)
{
    if (threadIdx.x == 0 && out_size > Tn * Hn) {
        float loss = 0.f;
        for (int e = 0; e < En; e++) {
            int a = 0;
            for (int b = 0; b < Bn; b++) a += g_cnt[e * Bn + b];
            loss += ((float)a / (float)Tn) * (g_imp[e] / (float)Tn);
        }
        out[Tn * Hn] = (float)En * loss;
    }
}

// ---------------- tf32 mma.sync GEMM: 128x128 tile, 8 warps, warp 64x32 ----------------
enum { KK = 0, KV = 1, KQ = 2, KF1 = 3, KF2 = 4, KSC = 5, KPV = 6, KO = 7 };

__device__ __forceinline__ uint32_t tf32_rna(float x) {
    uint32_t u;
    asm("cvt.rna.tf32.f32 %0, %1;" : "=r"(u) : "f"(x));
    return u;
}

__device__ __forceinline__ void mma_tf32_16x8x8(float* c, const uint32_t* a, const uint32_t* b) {
    asm volatile(
        "mma.sync.aligned.m16n8k8.row.col.f32.tf32.tf32.f32 "
        "{%0,%1,%2,%3}, {%4,%5,%6,%7}, {%8,%9}, {%0,%1,%2,%3};"
        : "+f"(c[0]), "+f"(c[1]), "+f"(c[2]), "+f"(c[3])
        : "r"(a[0]), "r"(a[1]), "r"(a[2]), "r"(a[3]), "r"(b[0]), "r"(b[1]));
}

#define PADW 136   // 136 mod 32 == 8 -> fragment reads (tg*8+grp) hit 32 distinct banks

template <int KIND>
__global__ __launch_bounds__(256, 2)
void gemm_kernel(const float* __restrict__ Xin, const float* __restrict__ W,
                 const float* __restrict__ bias, float* __restrict__ outp)
{
    constexpr bool BUCKET = (KIND != KK && KIND != KV);
    constexpr bool TRANSB = (KIND == KSC);
    constexpr int  KDIM = (KIND == KF2) ? Fn : (KIND == KPV ? Sn : Hn);
    constexpr int  LDB  = (KIND == KF1) ? Fn : Hn;
    constexpr int  NDIM = (KIND == KF1) ? Fn : (KIND == KSC ? Sn : Hn);

    const int tid  = threadIdx.x;
    const int wid  = tid >> 5;
    const int lane = tid & 31;
    const int z = blockIdx.z;
    int e, bb = 0, M;
    if (BUCKET) {
        e = z >> 2; bb = z & 3;
        M = g_cnt[z];
        if ((int)(blockIdx.x * 128) >= M) return;
    } else {
        e = z; M = Tn;
    }

    const float* Bptr;
    if      (KIND == KK || KIND == KV || KIND == KQ || KIND == KO) Bptr = W + (size_t)e * Hn * Hn;
    else if (KIND == KF1) Bptr = W + (size_t)e * Hn * Fn;
    else if (KIND == KF2) Bptr = W + (size_t)e * Fn * Hn;
    else if (KIND == KSC) Bptr = g_K + ((size_t)e * Tn + (size_t)bb * Sn) * Hn;
    else                  Bptr = g_V + ((size_t)e * Tn + (size_t)bb * Sn) * Hn;  // KPV

    const int row0 = blockIdx.x * 128;
    const int col0 = blockIdx.y * 128;

    // ---- loader indices ----
    const int lr  = tid >> 1;          // A row 0..127
    const int lk8 = (tid & 1) * 8;     // A k offset 0/8
    const int grow = row0 + lr;
    const bool aval = grow < M;
    const float* aRow = nullptr;
    if (aval) {
        if      (KIND == KQ || KIND == KF1)  aRow = Xin + (size_t)g_tok[z * CAPn + grow] * Hn;
        else if (KIND == KK || KIND == KV)   aRow = Xin + (size_t)grow * Hn;
        else if (KIND == KF2)                aRow = g_h1 + ((size_t)z * CAPn + grow) * Fn;
        else if (KIND == KSC)                aRow = g_q  + ((size_t)z * CAPn + grow) * Hn;
        else if (KIND == KPV)                aRow = g_sc + ((size_t)z * CAPn + grow) * Sn;
        else                                 aRow = g_a  + ((size_t)z * CAPn + grow) * Hn;  // KO
    }
    const int bkr = tid >> 4;          // B k row 0..15 (normal)
    const int bcc = (tid & 15) * 8;    // B col base (normal)
    const int tbc  = tid >> 1;         // B col 0..127 (trans)
    const int tbk8 = (tid & 1) * 8;    // B k offset (trans)

    __shared__ __align__(16) float As[16][PADW];
    __shared__ __align__(16) float Bs[16][PADW];

    float acc[4][4][4];
#pragma unroll
    for (int i = 0; i < 4; i++)
#pragma unroll
        for (int j = 0; j < 4; j++)
#pragma unroll
            for (int k = 0; k < 4; k++) acc[i][j][k] = 0.f;

    const int wm  = (wid >> 2) * 64;   // warp m offset
    const int wn  = (wid & 3) * 32;    // warp n offset
    const int grp = lane >> 2;
    const int tg  = lane & 3;

    // ---- prefetch chunk 0 ----
    float4 pa0 = make_float4(0.f,0.f,0.f,0.f), pa1 = pa0, pb0 = pa0, pb1 = pa0;
    if (aval) {
        pa0 = *(const float4*)(aRow + lk8);
        pa1 = *(const float4*)(aRow + lk8 + 4);
    }
    if (!TRANSB) {
        const float* src = Bptr + (size_t)bkr * LDB + col0 + bcc;
        pb0 = *(const float4*)src;
        pb1 = *(const float4*)(src + 4);
    } else {
        const float* src = Bptr + (size_t)(col0 + tbc) * LDB + tbk8;
        pb0 = *(const float4*)src;
        pb1 = *(const float4*)(src + 4);
    }

    for (int kt = 0; kt < KDIM; kt += 16) {
        // store prefetched tile (with tf32 rounding baked in)
        {
            float av[8] = {pa0.x,pa0.y,pa0.z,pa0.w,pa1.x,pa1.y,pa1.z,pa1.w};
#pragma unroll
            for (int i = 0; i < 8; i++)
                As[lk8 + i][lr] = __uint_as_float(tf32_rna(av[i]));
            if (!TRANSB) {
                float bv[8] = {pb0.x,pb0.y,pb0.z,pb0.w,pb1.x,pb1.y,pb1.z,pb1.w};
#pragma unroll
                for (int i = 0; i < 8; i++)
                    Bs[bkr][bcc + i] = __uint_as_float(tf32_rna(bv[i]));
            } else {
                float bv[8] = {pb0.x,pb0.y,pb0.z,pb0.w,pb1.x,pb1.y,pb1.z,pb1.w};
#pragma unroll
                for (int i = 0; i < 8; i++)
                    Bs[tbk8 + i][tbc] = __uint_as_float(tf32_rna(bv[i]));
            }
        }
        __syncthreads();

        // prefetch next chunk
        if (kt + 16 < KDIM) {
            if (aval) {
                pa0 = *(const float4*)(aRow + kt + 16 + lk8);
                pa1 = *(const float4*)(aRow + kt + 16 + lk8 + 4);
            }
            if (!TRANSB) {
                const float* src = Bptr + (size_t)(kt + 16 + bkr) * LDB + col0 + bcc;
                pb0 = *(const float4*)src;
                pb1 = *(const float4*)(src + 4);
            } else {
                const float* src = Bptr + (size_t)(col0 + tbc) * LDB + kt + 16 + tbk8;
                pb0 = *(const float4*)src;
                pb1 = *(const float4*)(src + 4);
            }
        }

        // compute 2 k8-steps
#pragma unroll
        for (int ks = 0; ks < 16; ks += 8) {
            uint32_t af[4][4], bf[4][2];
#pragma unroll
            for (int mt = 0; mt < 4; mt++) {
                const int m = wm + mt * 16 + grp;
                af[mt][0] = __float_as_uint(As[ks + tg][m]);
                af[mt][1] = __float_as_uint(As[ks + tg][m + 8]);
                af[mt][2] = __float_as_uint(As[ks + tg + 4][m]);
                af[mt][3] = __float_as_uint(As[ks + tg + 4][m + 8]);
            }
#pragma unroll
            for (int nt = 0; nt < 4; nt++) {
                const int n = wn + nt * 8 + grp;
                bf[nt][0] = __float_as_uint(Bs[ks + tg][n]);
                bf[nt][1] = __float_as_uint(Bs[ks + tg + 4][n]);
            }
#pragma unroll
            for (int mt = 0; mt < 4; mt++)
#pragma unroll
                for (int nt = 0; nt < 4; nt++)
                    mma_tf32_16x8x8(acc[mt][nt], af[mt], bf[nt]);
        }
        __syncthreads();
    }

    // ---------------- epilogue ----------------
    // lane owns rows: row0+wm+mt*16+grp (+8), cols: col0+wn+nt*8+tg*2 (+1)
#pragma unroll
    for (int mt = 0; mt < 4; mt++) {
#pragma unroll
        for (int half = 0; half < 2; half++) {
            const int r = row0 + wm + mt * 16 + grp + half * 8;
            if (BUCKET && r >= M) continue;

            if (KIND == KK || KIND == KV) {
                float* C = (KIND == KK ? g_K : g_V) + (size_t)e * Tn * Hn + (size_t)r * Hn;
                const float* bp = bias + (size_t)e * Hn;
#pragma unroll
                for (int nt = 0; nt < 4; nt++) {
                    const int c = col0 + wn + nt * 8 + tg * 2;
                    float2 bv = *(const float2*)(bp + c);
                    float2 v = make_float2(acc[mt][nt][half*2]   + bv.x,
                                           acc[mt][nt][half*2+1] + bv.y);
                    *(float2*)(C + c) = v;
                }
            } else if (KIND == KQ) {
                float* C = g_q + ((size_t)z * CAPn + r) * Hn;
                const float* bp = bias + (size_t)e * Hn;
#pragma unroll
                for (int nt = 0; nt < 4; nt++) {
                    const int c = col0 + wn + nt * 8 + tg * 2;
                    float2 bv = *(const float2*)(bp + c);
                    float2 v = make_float2(acc[mt][nt][half*2]   + bv.x,
                                           acc[mt][nt][half*2+1] + bv.y);
                    *(float2*)(C + c) = v;
                }
            } else if (KIND == KF1) {
                float* C = g_h1 + ((size_t)z * CAPn + r) * Fn;
                const float* bp = bias + (size_t)e * Fn;
#pragma unroll
                for (int nt = 0; nt < 4; nt++) {
                    const int c = col0 + wn + nt * 8 + tg * 2;
                    float2 bv = *(const float2*)(bp + c);
                    float t0 = acc[mt][nt][half*2]   + bv.x;
                    float t1 = acc[mt][nt][half*2+1] + bv.y;
                    float2 v;
                    v.x = 0.5f * t0 * (1.0f + erff(t0 * 0.70710678118654752f));
                    v.y = 0.5f * t1 * (1.0f + erff(t1 * 0.70710678118654752f));
                    *(float2*)(C + c) = v;
                }
            } else if (KIND == KF2) {
                float* C = g_h2 + ((size_t)z * CAPn + r) * Hn;
                const float* bp = bias + (size_t)e * Hn;
#pragma unroll
                for (int nt = 0; nt < 4; nt++) {
                    const int c = col0 + wn + nt * 8 + tg * 2;
                    float2 bv = *(const float2*)(bp + c);
                    float2 v = make_float2(acc[mt][nt][half*2]   + bv.x,
                                           acc[mt][nt][half*2+1] + bv.y);
                    *(float2*)(C + c) = v;
                }
            } else if (KIND == KSC) {
                const float scl = 0.044194173824159216f;  // 1/sqrt(512)
                float* C = g_sc + ((size_t)z * CAPn + r) * Sn;
#pragma unroll
                for (int nt = 0; nt < 4; nt++) {
                    const int c = col0 + wn + nt * 8 + tg * 2;
                    float2 v = make_float2(acc[mt][nt][half*2]   * scl,
                                           acc[mt][nt][half*2+1] * scl);
                    *(float2*)(C + c) = v;
                }
            } else if (KIND == KPV) {
                float* C = g_a + ((size_t)z * CAPn + r) * Hn;
#pragma unroll
                for (int nt = 0; nt < 4; nt++) {
                    const int c = col0 + wn + nt * 8 + tg * 2;
                    float2 v = make_float2(acc[mt][nt][half*2],
                                           acc[mt][nt][half*2+1]);
                    *(float2*)(C + c) = v;
                }
            } else {  // KO
                const int tok = g_tok[z * CAPn + r];
                const float wt = g_wt[z * CAPn + r];
                const float* bp = bias + (size_t)e * Hn;
                const float* h2 = g_h2 + ((size_t)z * CAPn + r) * Hn;
                float* od = outp + (size_t)tok * Hn;
#pragma unroll
                for (int nt = 0; nt < 4; nt++) {
                    const int c = col0 + wn + nt * 8 + tg * 2;
                    float v0 = acc[mt][nt][half*2]   + bp[c]   + h2[c];
                    float v1 = acc[mt][nt][half*2+1] + bp[c+1] + h2[c+1];
                    atomicAdd(od + c,     wt * v0);
                    atomicAdd(od + c + 1, wt * v1);
                }
            }
        }
    }
}

// ---------------- launch ----------------
extern "C" void kernel_launch(void* const* d_in, const int* in_sizes, int n_in,
                              void* d_out, int out_size)
{
    const float* x    = (const float*)d_in[0];
    const float* Wg   = (const float*)d_in[1];
    const float* bg   = (const float*)d_in[2];
    const float* fc1w = (const float*)d_in[3];
    const float* fc1b = (const float*)d_in[4];
    const float* fc2w = (const float*)d_in[5];
    const float* fc2b = (const float*)d_in[6];
    const float* qw   = (const float*)d_in[7];
    const float* qb   = (const float*)d_in[8];
    const float* kw   = (const float*)d_in[9];
    const float* kb   = (const float*)d_in[10];
    const float* vw   = (const float*)d_in[11];
    const float* vb   = (const float*)d_in[12];
    const float* ow   = (const float*)d_in[13];
    const float* ob   = (const float*)d_in[14];
    float* out = (float*)d_out;

    reset_kernel<<<1, 64>>>();
    zero_kernel<<<(out_size + 255) / 256, 256>>>(out, out_size);
    router_kernel<<<Tn / 8, 256>>>(x, Wg, bg);

    dim3 gkv(Tn / 128, Hn / 128, En);
    gemm_kernel<KK><<<gkv, 256>>>(x, kw, kb, nullptr);
    gemm_kernel<KV><<<gkv, 256>>>(x, vw, vb, nullptr);

    dim3 gq(CAPn / 128, Hn / 128, NBUCK);
    gemm_kernel<KQ><<<gq, 256>>>(x, qw, qb, nullptr);

    dim3 gf1(CAPn / 128, Fn / 128, NBUCK);
    gemm_kernel<KF1><<<gf1, 256>>>(x, fc1w, fc1b, nullptr);

    dim3 gf2(CAPn / 128, Hn / 128, NBUCK);
    gemm_kernel<KF2><<<gf2, 256>>>(nullptr, fc2w, fc2b, nullptr);

    dim3 gsc(CAPn / 128, Sn / 128, NBUCK);
    gemm_kernel<KSC><<<gsc, 256>>>(nullptr, nullptr, nullptr, nullptr);

    softmax_kernel<<<NBUCK * CAPn, 256>>>();

    dim3 gpv(CAPn / 128, Hn / 128, NBUCK);
    gemm_kernel<KPV><<<gpv, 256>>>(nullptr, nullptr, nullptr, nullptr);

    dim3 go(CAPn / 128, Hn / 128, NBUCK);
    gemm_kernel<KO><<<go, 256>>>(nullptr, ow, ob, out);

    finalize_kernel<<<1, 32>>>(out, out_size);
}